// round 3
// baseline (speedup 1.0000x reference)
#include <cuda_runtime.h>
#include <cstdint>

// Problem constants
#define B_    32
#define H_    14
#define W_    14
#define L_    196          // H*W
#define NPOS  6272         // B*L
#define CIN   1024
#define WIDTH 256
#define OUTC  1024
#define KC    16           // codewords per codebook
#define TILE_N 32          // positions per block

// ---------------- scratch (static device allocations only) ----------------
__device__ float g_out1[WIDTH * NPOS];   // channel-major [c][n]
__device__ float g_out2[WIDTH * NPOS];
__device__ float g_out3[OUTC  * NPOS];
__device__ float g_sc1[WIDTH], g_sh1[WIDTH];
__device__ float g_sc2[WIDTH], g_sh2[WIDTH];
__device__ float g_sc3[OUTC],  g_sh3[OUTC];

// ======================= AMM layer 1 (1x1, ncb=256, sub=4) =================
__global__ __launch_bounds__(256) void amm1_kernel(
    const float* __restrict__ x, const float* __restrict__ cent,
    const float* __restrict__ lut, const float* __restrict__ invt_p)
{
    __shared__ float lut_s[KC * WIDTH];     // 16 KB
    __shared__ float attn_s[TILE_N * 17];   // padded rows
    __shared__ float xv_s[4 * TILE_N];

    const int t  = threadIdx.x;
    const int n0 = blockIdx.x * TILE_N;
    const float invt = __ldg(invt_p);

    // accumulate mapping: 4 columns x 8 positions per thread
    const int po = t & 63;     // column group: cols po*4 .. po*4+3
    const int pn = t >> 6;     // position group: pos pn*8 .. pn*8+7
    float acc[8][4];
#pragma unroll
    for (int i = 0; i < 8; ++i)
#pragma unroll
        for (int q = 0; q < 4; ++q) acc[i][q] = 0.f;

    // xv loader mapping (threads 0..127)
    const int lj  = t >> 5;
    const int lnl = t & 31;
    const int ln  = n0 + lnl;
    const int lb  = ln / L_;
    const int ll  = ln - lb * L_;
    const float* xbase = x + (size_t)lb * CIN * L_ + ll;

    // scoring mapping: warp sw, 16-lane group grp, codeword kk
    const int sw   = t >> 5;
    const int lane = t & 31;
    const int grp  = lane >> 4;
    const int kk   = lane & 15;

    for (int c = 0; c < 256; ++c) {
        // prefetch LUT slice into registers (latency hidden behind scoring)
        float4 lr[4];
        const float4* lp = (const float4*)(lut + (size_t)c * KC * WIDTH);
#pragma unroll
        for (int i = 0; i < 4; ++i) lr[i] = __ldg(lp + t + i * 256);

        if (lj < 4)
            xv_s[lj * TILE_N + lnl] = __ldg(xbase + (c * 4 + lj) * L_);
        __syncthreads();

        // scoring + softmax (each 16-lane group handles one position per pass)
        {
            const float* cp = cent + (size_t)(c * KC + kk) * 4;
            const float c0 = __ldg(cp + 0), c1 = __ldg(cp + 1);
            const float c2 = __ldg(cp + 2), c3 = __ldg(cp + 3);
            const float nrm = c0 * c0 + c1 * c1 + c2 * c2 + c3 * c3;
#pragma unroll
            for (int pass = 0; pass < 2; ++pass) {
                const int nl = pass * 16 + sw * 2 + grp;
                float s = c0 * xv_s[0 * TILE_N + nl] + c1 * xv_s[1 * TILE_N + nl]
                        + c2 * xv_s[2 * TILE_N + nl] + c3 * xv_s[3 * TILE_N + nl];
                s = (2.f * s - nrm) * invt;
                float m = s;
#pragma unroll
                for (int d = 8; d; d >>= 1)
                    m = fmaxf(m, __shfl_xor_sync(0xffffffffu, m, d, 16));
                const float e = __expf(s - m);
                float sum = e;
#pragma unroll
                for (int d = 8; d; d >>= 1)
                    sum += __shfl_xor_sync(0xffffffffu, sum, d, 16);
                attn_s[nl * 17 + kk] = e / sum;
            }
        }
#pragma unroll
        for (int i = 0; i < 4; ++i) ((float4*)lut_s)[t + i * 256] = lr[i];
        __syncthreads();

        // 32x16x256 accumulate from SMEM, register-blocked
#pragma unroll
        for (int k = 0; k < KC; ++k) {
            const float4 bv = ((const float4*)lut_s)[k * 64 + po];
#pragma unroll
            for (int i = 0; i < 8; ++i) {
                const float a = attn_s[(pn * 8 + i) * 17 + k];
                acc[i][0] += a * bv.x;
                acc[i][1] += a * bv.y;
                acc[i][2] += a * bv.z;
                acc[i][3] += a * bv.w;
            }
        }
        __syncthreads();
    }

    // store channel-major
#pragma unroll
    for (int q = 0; q < 4; ++q) {
        const int o = po * 4 + q;
        float* dst = g_out1 + (size_t)o * NPOS + n0 + pn * 8;
#pragma unroll
        for (int i = 0; i < 8; ++i) dst[i] = acc[i][q];
    }
}

// ============ AMM layer 2 (3x3 patches, ncb=256, sub=9, bn1+relu fused) ====
__global__ __launch_bounds__(256) void amm2_kernel(
    const float* __restrict__ cent, const float* __restrict__ lut,
    const float* __restrict__ invt_p)
{
    __shared__ float lut_s[KC * WIDTH];
    __shared__ float attn_s[TILE_N * 17];
    __shared__ float xv_s[9 * TILE_N];

    const int t  = threadIdx.x;
    const int n0 = blockIdx.x * TILE_N;
    const float invt = __ldg(invt_p);

    const int po = t & 63;
    const int pn = t >> 6;
    float acc[8][4];
#pragma unroll
    for (int i = 0; i < 8; ++i)
#pragma unroll
        for (int q = 0; q < 4; ++q) acc[i][q] = 0.f;

    // precompute patch-gather slots (288 entries over 256 threads -> 2 rounds)
    int posn[2]; bool vld[2];
#pragma unroll
    for (int r = 0; r < 2; ++r) {
        const int idx = t + r * 256;
        vld[r] = false; posn[r] = 0;
        if (idx < 9 * TILE_N) {
            const int s9 = idx >> 5, nl = idx & 31;
            const int n = n0 + nl;
            const int b = n / L_;
            const int l = n - b * L_;
            const int h = l / W_, w = l - (l / W_) * W_;
            const int hh = h + s9 / 3 - 1;
            const int ww = w + s9 % 3 - 1;
            if (hh >= 0 && hh < H_ && ww >= 0 && ww < W_) {
                vld[r]  = true;
                posn[r] = b * L_ + hh * W_ + ww;
            }
        }
    }

    const int sw = t >> 5, lane = t & 31, grp = lane >> 4, kk = lane & 15;

    for (int c = 0; c < 256; ++c) {
        float4 lr[4];
        const float4* lp = (const float4*)(lut + (size_t)c * KC * WIDTH);
#pragma unroll
        for (int i = 0; i < 4; ++i) lr[i] = __ldg(lp + t + i * 256);

        const float sc1 = g_sc1[c], sh1 = g_sh1[c];
#pragma unroll
        for (int r = 0; r < 2; ++r) {
            const int idx = t + r * 256;
            if (idx < 9 * TILE_N) {
                float v = 0.f;
                if (vld[r])
                    v = fmaxf(g_out1[(size_t)c * NPOS + posn[r]] * sc1 + sh1, 0.f);
                xv_s[idx] = v;
            }
        }
        __syncthreads();

        {
            const float* cp = cent + (size_t)(c * KC + kk) * 9;
            float cw[9]; float nrm = 0.f;
#pragma unroll
            for (int j = 0; j < 9; ++j) { cw[j] = __ldg(cp + j); nrm += cw[j] * cw[j]; }
#pragma unroll
            for (int pass = 0; pass < 2; ++pass) {
                const int nl = pass * 16 + sw * 2 + grp;
                float s = 0.f;
#pragma unroll
                for (int j = 0; j < 9; ++j) s += cw[j] * xv_s[j * TILE_N + nl];
                s = (2.f * s - nrm) * invt;
                float m = s;
#pragma unroll
                for (int d = 8; d; d >>= 1)
                    m = fmaxf(m, __shfl_xor_sync(0xffffffffu, m, d, 16));
                const float e = __expf(s - m);
                float sum = e;
#pragma unroll
                for (int d = 8; d; d >>= 1)
                    sum += __shfl_xor_sync(0xffffffffu, sum, d, 16);
                attn_s[nl * 17 + kk] = e / sum;
            }
        }
#pragma unroll
        for (int i = 0; i < 4; ++i) ((float4*)lut_s)[t + i * 256] = lr[i];
        __syncthreads();

#pragma unroll
        for (int k = 0; k < KC; ++k) {
            const float4 bv = ((const float4*)lut_s)[k * 64 + po];
#pragma unroll
            for (int i = 0; i < 8; ++i) {
                const float a = attn_s[(pn * 8 + i) * 17 + k];
                acc[i][0] += a * bv.x;
                acc[i][1] += a * bv.y;
                acc[i][2] += a * bv.z;
                acc[i][3] += a * bv.w;
            }
        }
        __syncthreads();
    }

#pragma unroll
    for (int q = 0; q < 4; ++q) {
        const int o = po * 4 + q;
        float* dst = g_out2 + (size_t)o * NPOS + n0 + pn * 8;
#pragma unroll
        for (int i = 0; i < 8; ++i) dst[i] = acc[i][q];
    }
}

// ======= AMM layer 3 (1x1, ncb=64, sub=4, out=1024, bn2+relu fused) ========
// grid.y splits the 1024 output columns into 4 chunks of 256
__global__ __launch_bounds__(256) void amm3_kernel(
    const float* __restrict__ cent, const float* __restrict__ lut,
    const float* __restrict__ invt_p)
{
    __shared__ float lut_s[KC * WIDTH];
    __shared__ float attn_s[TILE_N * 17];
    __shared__ float xv_s[4 * TILE_N];

    const int t  = threadIdx.x;
    const int n0 = blockIdx.x * TILE_N;
    const int obase = blockIdx.y << 8;
    const float invt = __ldg(invt_p);

    const int po = t & 63;
    const int pn = t >> 6;
    float acc[8][4];
#pragma unroll
    for (int i = 0; i < 8; ++i)
#pragma unroll
        for (int q = 0; q < 4; ++q) acc[i][q] = 0.f;

    const int lj  = t >> 5;
    const int lnl = t & 31;
    const int ln  = n0 + lnl;

    const int k0 = t >> 6;   // lut-row base for staging
    const int o4 = t & 63;   // float4 column within row

    const int sw = t >> 5, lane = t & 31, grp = lane >> 4, kk = lane & 15;

    for (int c = 0; c < 64; ++c) {
        float4 lr[4];
#pragma unroll
        for (int i = 0; i < 4; ++i)
            lr[i] = __ldg((const float4*)(lut + (size_t)(c * KC + k0 + i * 4) * OUTC + obase) + o4);

        if (lj < 4) {
            const int ch = c * 4 + lj;
            const float v = g_out2[(size_t)ch * NPOS + ln] * g_sc2[ch] + g_sh2[ch];
            xv_s[lj * TILE_N + lnl] = fmaxf(v, 0.f);
        }
        __syncthreads();

        {
            const float* cp = cent + (size_t)(c * KC + kk) * 4;
            const float c0 = __ldg(cp + 0), c1 = __ldg(cp + 1);
            const float c2 = __ldg(cp + 2), c3 = __ldg(cp + 3);
            const float nrm = c0 * c0 + c1 * c1 + c2 * c2 + c3 * c3;
#pragma unroll
            for (int pass = 0; pass < 2; ++pass) {
                const int nl = pass * 16 + sw * 2 + grp;
                float s = c0 * xv_s[0 * TILE_N + nl] + c1 * xv_s[1 * TILE_N + nl]
                        + c2 * xv_s[2 * TILE_N + nl] + c3 * xv_s[3 * TILE_N + nl];
                s = (2.f * s - nrm) * invt;
                float m = s;
#pragma unroll
                for (int d = 8; d; d >>= 1)
                    m = fmaxf(m, __shfl_xor_sync(0xffffffffu, m, d, 16));
                const float e = __expf(s - m);
                float sum = e;
#pragma unroll
                for (int d = 8; d; d >>= 1)
                    sum += __shfl_xor_sync(0xffffffffu, sum, d, 16);
                attn_s[nl * 17 + kk] = e / sum;
            }
        }
#pragma unroll
        for (int i = 0; i < 4; ++i) ((float4*)lut_s)[t + i * 256] = lr[i];
        __syncthreads();

#pragma unroll
        for (int k = 0; k < KC; ++k) {
            const float4 bv = ((const float4*)lut_s)[k * 64 + po];
#pragma unroll
            for (int i = 0; i < 8; ++i) {
                const float a = attn_s[(pn * 8 + i) * 17 + k];
                acc[i][0] += a * bv.x;
                acc[i][1] += a * bv.y;
                acc[i][2] += a * bv.z;
                acc[i][3] += a * bv.w;
            }
        }
        __syncthreads();
    }

#pragma unroll
    for (int q = 0; q < 4; ++q) {
        const int o = obase + po * 4 + q;
        float* dst = g_out3 + (size_t)o * NPOS + n0 + pn * 8;
#pragma unroll
        for (int i = 0; i < 8; ++i) dst[i] = acc[i][q];
    }
}

// ================== BN batch-stats (one block per channel) =================
__global__ __launch_bounds__(256) void bn_stats_kernel(
    int which, const float* __restrict__ gw, const float* __restrict__ bw)
{
    const float* data; float* scale; float* shift;
    if (which == 0)      { data = g_out1; scale = g_sc1; shift = g_sh1; }
    else if (which == 1) { data = g_out2; scale = g_sc2; shift = g_sh2; }
    else                 { data = g_out3; scale = g_sc3; shift = g_sh3; }

    const int c = blockIdx.x, t = threadIdx.x;
    const float* p = data + (size_t)c * NPOS;
    float s = 0.f, s2 = 0.f;
    for (int i = t; i < NPOS; i += 256) {
        const float v = p[i];
        s += v; s2 += v * v;
    }
#pragma unroll
    for (int d = 16; d; d >>= 1) {
        s  += __shfl_xor_sync(0xffffffffu, s,  d);
        s2 += __shfl_xor_sync(0xffffffffu, s2, d);
    }
    __shared__ float sh_s[8], sh_s2[8];
    if ((t & 31) == 0) { sh_s[t >> 5] = s; sh_s2[t >> 5] = s2; }
    __syncthreads();
    if (t == 0) {
        s = 0.f; s2 = 0.f;
#pragma unroll
        for (int i = 0; i < 8; ++i) { s += sh_s[i]; s2 += sh_s2[i]; }
        const float m   = s  * (1.f / NPOS);
        const float var = s2 * (1.f / NPOS) - m * m;
        const float sc  = __ldg(gw + c) * rsqrtf(var + 1e-5f);
        scale[c] = sc;
        shift[c] = __ldg(bw + c) - m * sc;
    }
}

// ============== final: bn3 + residual + relu, channel-major out ============
__global__ __launch_bounds__(256) void final_kernel(
    const float* __restrict__ x, float* __restrict__ out)
{
    const int idx = blockIdx.x * 256 + threadIdx.x;
    if (idx >= B_ * OUTC * L_) return;
    const int l = idx % L_;
    const int c = (idx / L_) % OUTC;
    const int b = idx / (L_ * OUTC);
    const int n = b * L_ + l;
    const float v = g_out3[(size_t)c * NPOS + n] * g_sc3[c] + g_sh3[c] + x[idx];
    out[idx] = fmaxf(v, 0.f);
}

// ==========================================================================
extern "C" void kernel_launch(void* const* d_in, const int* in_sizes, int n_in,
                              void* d_out, int out_size)
{
    (void)in_sizes; (void)n_in; (void)out_size;
    const float* x    = (const float*)d_in[0];
    const float* c1c  = (const float*)d_in[1];
    const float* c1l  = (const float*)d_in[2];
    const float* c1t  = (const float*)d_in[3];
    const float* c2c  = (const float*)d_in[4];
    const float* c2l  = (const float*)d_in[5];
    const float* c2t  = (const float*)d_in[6];
    const float* c3c  = (const float*)d_in[7];
    const float* c3l  = (const float*)d_in[8];
    const float* c3t  = (const float*)d_in[9];
    const float* bn1g = (const float*)d_in[10];
    const float* bn1b = (const float*)d_in[11];
    const float* bn2g = (const float*)d_in[12];
    const float* bn2b = (const float*)d_in[13];
    const float* bn3g = (const float*)d_in[14];
    const float* bn3b = (const float*)d_in[15];
    float* out = (float*)d_out;

    amm1_kernel<<<NPOS / TILE_N, 256>>>(x, c1c, c1l, c1t);
    bn_stats_kernel<<<WIDTH, 256>>>(0, bn1g, bn1b);
    amm2_kernel<<<NPOS / TILE_N, 256>>>(c2c, c2l, c2t);
    bn_stats_kernel<<<WIDTH, 256>>>(1, bn2g, bn2b);
    amm3_kernel<<<dim3(NPOS / TILE_N, 4), 256>>>(c3c, c3l, c3t);
    bn_stats_kernel<<<OUTC, 256>>>(2, bn3g, bn3b);
    final_kernel<<<(B_ * OUTC * L_ + 255) / 256, 256>>>(x, out);
}